// round 13
// baseline (speedup 1.0000x reference)
#include <cuda_runtime.h>

#define Bn  2
#define Sn  192
#define Dn  128
#define DIN 1024
#define BSn (Bn*Sn)                       // 384 rows
#define SZo ((long)Bn*Sn*Sn*Sn)           // 14,155,776 elements per output tensor

typedef unsigned long long ull;
union F4U { float4 f; ull u[2]; };

__device__ __forceinline__ ull ffma2(ull a, ull b, ull c) {
    ull d;
    asm("fma.rn.f32x2 %0, %1, %2, %3;" : "=l"(d) : "l"(a), "l"(b), "l"(c));
    return d;
}

// ---- scratch (device globals: allocation-free contract) ----
__device__ float g_mlp[3*BSn*Dn];         // p, sh, st        (576 KB)
__device__ float g_wz[BSn*Dn*Dn];         // wz / u scratch   (25.2 MB)
__device__ float g_t [BSn*Sn*Dn];         // t  / v scratch   (37.7 MB)

// ============================================================================
// MLP: C = leaky_relu(x @ W + b), 64x64 tiles, K=1024. grid(6,2,3)  (small)
// ============================================================================
__global__ __launch_bounds__(256) void mlp_kernel(
    const float* __restrict__ x,
    const float* __restrict__ W0, const float* __restrict__ b0,
    const float* __restrict__ W1, const float* __restrict__ b1,
    const float* __restrict__ W2, const float* __restrict__ b2)
{
    const int mt = blockIdx.x, nt = blockIdx.y, w = blockIdx.z;
    const float* W    = (w == 0) ? W0 : (w == 1) ? W1 : W2;
    const float* bias = (w == 0) ? b0 : (w == 1) ? b1 : b2;
    float* C = g_mlp + (long)w * BSn * Dn;

    __shared__ float As[64][17];
    __shared__ float Bs[16][65];
    const int tid = threadIdx.x;
    const int tx = tid & 15, ty = tid >> 4;
    const int m0 = mt * 64, n0 = nt * 64;
    float acc[4][4] = {};

    for (int k0 = 0; k0 < DIN; k0 += 16) {
        {
            int mm = tid >> 2, kk = (tid & 3) << 2;
            float4 v = *(const float4*)(x + (long)(m0 + mm) * DIN + k0 + kk);
            As[mm][kk] = v.x; As[mm][kk+1] = v.y; As[mm][kk+2] = v.z; As[mm][kk+3] = v.w;
        }
        {
            int kk = tid >> 4, nn = (tid & 15) << 2;
            float4 v = *(const float4*)(W + (long)(k0 + kk) * Dn + n0 + nn);
            Bs[kk][nn] = v.x; Bs[kk][nn+1] = v.y; Bs[kk][nn+2] = v.z; Bs[kk][nn+3] = v.w;
        }
        __syncthreads();
        #pragma unroll
        for (int kk = 0; kk < 16; kk++) {
            float a[4], b[4];
            #pragma unroll
            for (int r = 0; r < 4; r++) a[r] = As[ty*4 + r][kk];
            #pragma unroll
            for (int c = 0; c < 4; c++) b[c] = Bs[kk][tx + 16*c];
            #pragma unroll
            for (int r = 0; r < 4; r++)
                #pragma unroll
                for (int c = 0; c < 4; c++) acc[r][c] = fmaf(a[r], b[c], acc[r][c]);
        }
        __syncthreads();
    }
    #pragma unroll
    for (int r = 0; r < 4; r++) {
        int m = m0 + ty*4 + r;
        #pragma unroll
        for (int c = 0; c < 4; c++) {
            int n = n0 + tx + 16*c;
            float v = acc[r][c] + bias[n];
            v = (v > 0.f) ? v : 0.1f * v;
            C[(long)m * Dn + n] = v;
        }
    }
}

// ============================================================================
// FFMA2 GEMM engine: 64x64 tile, 64 threads, 8x8 micro, k-chunk 8.
// A tile stored DUPLICATED in smem (As[k][2m]=As[k][2m+1]) so the inner loop
// is 6x LDS.128 + 32x fma.rn.f32x2 per k-step, no pack instructions.
// ============================================================================

// Mainloop as a macro-style inline: computes acc[8][4] (ull pairs over n).
__device__ __forceinline__ void gemm64_mainloop(
    ull acc[8][4], float As[8][128], float Bs[8][64],
    const float* __restrict__ aPtr,            // Ab + (m0+tid)*lda   (k-contig)
    const float* __restrict__ Bb,
    int ldb, int n0, int bT, int K, int tid, int tx, int ty)
{
    // prefetch first tile into regs
    float4 ra0 = *(const float4*)(aPtr + 0);
    float4 ra1 = *(const float4*)(aPtr + 4);
    float4 rb0, rb1;
    if (!bT) {
        const float* bp = Bb + (long)ty * ldb + n0 + tx * 8;
        rb0 = *(const float4*)(bp);
        rb1 = *(const float4*)(bp + 4);
    } else {
        const float* bp = Bb + (long)(n0 + tid) * ldb;
        rb0 = *(const float4*)(bp);
        rb1 = *(const float4*)(bp + 4);
    }

    const int nIter = K >> 3;
    for (int it = 0; it < nIter; it++) {
        // ---- stage regs -> smem ----
        {
            float av[8] = {ra0.x, ra0.y, ra0.z, ra0.w, ra1.x, ra1.y, ra1.z, ra1.w};
            #pragma unroll
            for (int j = 0; j < 8; j++)
                *(float2*)&As[j][2*tid] = make_float2(av[j], av[j]);
        }
        if (!bT) {
            *(float4*)&Bs[ty][tx*8]     = rb0;
            *(float4*)&Bs[ty][tx*8 + 4] = rb1;
        } else {
            float bv[8] = {rb0.x, rb0.y, rb0.z, rb0.w, rb1.x, rb1.y, rb1.z, rb1.w};
            #pragma unroll
            for (int j = 0; j < 8; j++) Bs[j][tid] = bv[j];
        }
        __syncthreads();

        // ---- prefetch next tile ----
        if (it + 1 < nIter) {
            int k0n = (it + 1) << 3;
            ra0 = *(const float4*)(aPtr + k0n);
            ra1 = *(const float4*)(aPtr + k0n + 4);
            if (!bT) {
                const float* bp = Bb + (long)(k0n + ty) * ldb + n0 + tx * 8;
                rb0 = *(const float4*)(bp);
                rb1 = *(const float4*)(bp + 4);
            } else {
                const float* bp = Bb + (long)(n0 + tid) * ldb + k0n;
                rb0 = *(const float4*)(bp);
                rb1 = *(const float4*)(bp + 4);
            }
        }

        // ---- compute 8 k-steps ----
        #pragma unroll
        for (int kk = 0; kk < 8; kk++) {
            F4U a0, a1, a2, a3, b0, b1;
            a0.f = *(const float4*)&As[kk][ty*16 + 0];
            a1.f = *(const float4*)&As[kk][ty*16 + 4];
            a2.f = *(const float4*)&As[kk][ty*16 + 8];
            a3.f = *(const float4*)&As[kk][ty*16 + 12];
            b0.f = *(const float4*)&Bs[kk][tx*8];
            b1.f = *(const float4*)&Bs[kk][tx*8 + 4];
            ull av[8] = {a0.u[0], a0.u[1], a1.u[0], a1.u[1],
                         a2.u[0], a2.u[1], a3.u[0], a3.u[1]};
            ull bv[4] = {b0.u[0], b0.u[1], b1.u[0], b1.u[1]};
            #pragma unroll
            for (int r = 0; r < 8; r++)
                #pragma unroll
                for (int c = 0; c < 4; c++)
                    acc[r][c] = ffma2(av[r], bv[c], acc[r][c]);
        }
        __syncthreads();
    }
}

// Generic batched GEMM (direct C write).  grid(M/64, N/64, batch)
__global__ __launch_bounds__(64) void gemm64_kernel(
    const float* __restrict__ A, const float* __restrict__ Bm, float* __restrict__ C,
    int lda, int ldb, int ldc,
    int aDiv, long aStride, long bStride, long cStride, int bT, int K)
{
    const int mt = blockIdx.x, nt = blockIdx.y, z = blockIdx.z;
    const float* Ab = A + (long)(z / aDiv) * aStride;
    const float* Bb = Bm + (long)z * bStride;
    float* Cb = C + (long)z * cStride;
    const int m0 = mt * 64, n0 = nt * 64;
    const int tid = threadIdx.x, tx = tid & 7, ty = tid >> 3;

    __shared__ float As[8][128];
    __shared__ float Bs[8][64];
    ull acc[8][4] = {};

    gemm64_mainloop(acc, As, Bs, Ab + (long)(m0 + tid) * lda, Bb,
                    ldb, n0, bT, K, tid, tx, ty);

    #pragma unroll
    for (int r = 0; r < 8; r++) {
        F4U o0, o1;
        o0.u[0] = acc[r][0]; o0.u[1] = acc[r][1];
        o1.u[0] = acc[r][2]; o1.u[1] = acc[r][3];
        float* crow = Cb + (long)(m0 + ty*8 + r) * ldc + n0 + tx*8;
        *(float4*)(crow)     = o0.f;
        *(float4*)(crow + 4) = o1.f;
    }
}

// Output GEMM (NT): s[q][m,n] = sum_k A[q][m,k] * Y[b][n,k].  M=N=Sn, K=128.
// sym=1: upper tiles only, write value + mirror.  grid(3,3,BSn)
__global__ __launch_bounds__(64) void gemm_out64_kernel(
    const float* __restrict__ A, const float* __restrict__ Y,
    float* __restrict__ Out, int sym)
{
    const int bx = blockIdx.x, by = blockIdx.y, q = blockIdx.z;
    if (sym && bx > by) return;
    const float* Ab = A + (long)q * (Sn * Dn);
    const float* Bb = Y + (long)(q / Sn) * (Sn * Dn);
    float* Ob = Out + (long)q * (Sn * Sn);
    const int m0 = bx * 64, n0 = by * 64;
    const int tid = threadIdx.x, tx = tid & 7, ty = tid >> 3;

    __shared__ float As[8][128];
    __shared__ float Bs[8][64];
    __shared__ float Cs[64][68];
    ull acc[8][4] = {};

    gemm64_mainloop(acc, As, Bs, Ab + (long)(m0 + tid) * Dn, Bb,
                    Dn, n0, /*bT=*/1, Dn, tid, tx, ty);

    // stage C tile in smem (row pitch 68 floats = 272B, 16B-aligned)
    #pragma unroll
    for (int r = 0; r < 8; r++) {
        F4U o0, o1;
        o0.u[0] = acc[r][0]; o0.u[1] = acc[r][1];
        o1.u[0] = acc[r][2]; o1.u[1] = acc[r][3];
        *(float4*)&Cs[ty*8 + r][tx*8]     = o0.f;
        *(float4*)&Cs[ty*8 + r][tx*8 + 4] = o1.f;
    }
    __syncthreads();

    // write out: thread covers 4 consecutive cols (float4), 16 row-passes
    const int c4 = (tid & 15) * 4;       // column group
    const int rg = tid >> 4;             // row offset within pass
    if (!sym) {
        #pragma unroll
        for (int i = 0; i < 16; i++) {
            int r = i*4 + rg;
            *(float4*)&Ob[(long)(m0 + r) * Sn + n0 + c4] = *(float4*)&Cs[r][c4];
        }
    } else if (bx < by) {
        #pragma unroll
        for (int i = 0; i < 16; i++) {
            int r = i*4 + rg;
            *(float4*)&Ob[(long)(m0 + r) * Sn + n0 + c4] = *(float4*)&Cs[r][c4];
            float4 t = make_float4(Cs[c4][r], Cs[c4+1][r], Cs[c4+2][r], Cs[c4+3][r]);
            *(float4*)&Ob[(long)(n0 + r) * Sn + m0 + c4] = t;
        }
    } else {  // diagonal tile
        #pragma unroll
        for (int i = 0; i < 16; i++) {
            int r = i*4 + rg;
            float4 v;
            v.x = (r <= c4  ) ? Cs[r][c4  ] : Cs[c4  ][r];
            v.y = (r <= c4+1) ? Cs[r][c4+1] : Cs[c4+1][r];
            v.z = (r <= c4+2) ? Cs[r][c4+2] : Cs[c4+2][r];
            v.w = (r <= c4+3) ? Cs[r][c4+3] : Cs[c4+3][r];
            *(float4*)&Ob[(long)(m0 + r) * Sn + n0 + c4] = v;
        }
    }
}

// ============================================================================
// pt_cop mirror pass over output layout [b,x,y,z]: for x>y, out[b,x,y,:] = out[b,y,x,:]
// ============================================================================
__global__ void mirror_kernel(float* __restrict__ Out)
{
    const int x = blockIdx.x, b = blockIdx.y;
    for (int y = 0; y < x; y++) {
        long dst = ((long)(b * Sn + x) * Sn + y) * Sn;
        long src = ((long)(b * Sn + y) * Sn + x) * Sn;
        for (int z = threadIdx.x; z < Sn; z += blockDim.x)
            Out[dst + z] = Out[src + z];
    }
}

// ============================================================================
extern "C" void kernel_launch(void* const* d_in, const int* in_sizes, int n_in,
                              void* d_out, int out_size)
{
    const float* x  = (const float*)d_in[0];
    const float* Wp = (const float*)d_in[1];
    const float* bp = (const float*)d_in[2];
    const float* Wh = (const float*)d_in[3];
    const float* bh = (const float*)d_in[4];
    const float* Wt = (const float*)d_in[5];
    const float* bt = (const float*)d_in[6];
    const float* W_span_ph = (const float*)d_in[7];
    const float* W_span_pt = (const float*)d_in[8];
    const float* W_ph_sib  = (const float*)d_in[9];
    const float* W_pt_sib  = (const float*)d_in[10];
    const float* W_ph_cop  = (const float*)d_in[11];
    const float* W_pt_cop  = (const float*)d_in[12];
    float* out = (float*)d_out;

    float *mlpP, *wzP, *tP;
    cudaGetSymbolAddress((void**)&mlpP, g_mlp);
    cudaGetSymbolAddress((void**)&wzP,  g_wz);
    cudaGetSymbolAddress((void**)&tP,   g_t);
    const float* p  = mlpP;
    const float* sh = mlpP + BSn * Dn;
    const float* st = mlpP + 2 * BSn * Dn;

    // p, sh, st
    mlp_kernel<<<dim3(6, 2, 3), 256>>>(x, Wp, bp, Wh, bh, Wt, bt);

    // ---- type 1 (sym, layout [b,z,x,y]): span_psh, span_pt, ph_sib, pt_sib ----
    const float* Ws1[4] = {W_span_ph, W_span_pt, W_ph_sib, W_pt_sib};
    const float* Xs1[4] = {sh, sh, sh, st};
    const float* Ys1[4] = {st, st, sh, st};
    for (int t = 0; t < 4; t++) {
        // wz[r, i, j] = sum_k p[r,k] * w[i,k,j]   (batch over i)
        gemm64_kernel<<<dim3(6, 2, 128), 64>>>(p, Ws1[t], wzP,
            Dn, Dn, Dn*Dn, 1, 0L, (long)Dn*Dn, (long)Dn, 0, Dn);
        // t[q, x, j] = sum_i X[b,x,i] * wz[q,i,j]  (NN, batch over q=(b,z))
        gemm64_kernel<<<dim3(3, 2, 384), 64>>>(Xs1[t], wzP, tP,
            Dn, Dn, Dn, Sn, (long)Sn*Dn, (long)Dn*Dn, (long)Sn*Dn, 0, Dn);
        // s[q, x, y] = sum_j t[q,x,j] * Y[b,y,j]   (NT, symmetrized write)
        gemm_out64_kernel<<<dim3(3, 3, 384), 64>>>(tP, Ys1[t], out + (long)t * SZo, 1);
    }

    // ---- type 2 (co-parent, layout [b,x,y,z]): ph_cop, pt_cop ----
    const float* Ws2[2] = {W_ph_cop, W_pt_cop};
    const float* Zs2[2] = {sh, st};
    for (int t = 0; t < 2; t++) {
        // u[r, k, j] = sum_i p[r,i] * w[i,k,j]    (batch over k)
        gemm64_kernel<<<dim3(6, 2, 128), 64>>>(p, Ws2[t], wzP,
            Dn, Dn*Dn, Dn*Dn, 1, 0L, (long)Dn, (long)Dn, 0, Dn);
        // v[q, y, k] = sum_j p[b,y,j] * u[q,k,j]  (NT, batch over q=(b,x))
        gemm64_kernel<<<dim3(3, 2, 384), 64>>>(p, wzP, tP,
            Dn, Dn, Dn, Sn, (long)Sn*Dn, (long)Dn*Dn, (long)Sn*Dn, 1, Dn);
        // out[q, y, z] = sum_k v[q,y,k] * Z[b,z,k] (NT, full write, z contiguous)
        gemm_out64_kernel<<<dim3(3, 3, 384), 64>>>(tP, Zs2[t], out + (long)(4 + t) * SZo, 0);
    }
    // pt_cop: sym over (x,y) crosses batch planes -> mirror pass
    mirror_kernel<<<dim3(Sn, Bn), 192>>>(out + 5 * SZo);
}

// round 14
// speedup vs baseline: 1.0361x; 1.0361x over previous
#include <cuda_runtime.h>

#define Bn  2
#define Sn  192
#define Dn  128
#define DIN 1024
#define BSn (Bn*Sn)                       // 384 rows
#define SZo ((long)Bn*Sn*Sn*Sn)           // 14,155,776 elements per output tensor

typedef unsigned long long ull;
union F4U { float4 f; ull u[2]; };

__device__ __forceinline__ ull ffma2(ull a, ull b, ull c) {
    ull d;
    asm("fma.rn.f32x2 %0, %1, %2, %3;" : "=l"(d) : "l"(a), "l"(b), "l"(c));
    return d;
}

// ---- scratch (device globals: allocation-free contract) ----
__device__ float g_mlp[3*BSn*Dn];         // p, sh, st        (576 KB)
__device__ float g_wz[BSn*Dn*Dn];         // wz / u scratch   (25.2 MB)
__device__ float g_t [BSn*Sn*Dn];         // t  / v scratch   (37.7 MB)

// ============================================================================
// MLP: C = leaky_relu(x @ W + b), 64x64 tiles, K=1024. grid(6,2,3)  (small)
// ============================================================================
__global__ __launch_bounds__(256) void mlp_kernel(
    const float* __restrict__ x,
    const float* __restrict__ W0, const float* __restrict__ b0,
    const float* __restrict__ W1, const float* __restrict__ b1,
    const float* __restrict__ W2, const float* __restrict__ b2)
{
    const int mt = blockIdx.x, nt = blockIdx.y, w = blockIdx.z;
    const float* W    = (w == 0) ? W0 : (w == 1) ? W1 : W2;
    const float* bias = (w == 0) ? b0 : (w == 1) ? b1 : b2;
    float* C = g_mlp + (long)w * BSn * Dn;

    __shared__ float As[64][17];
    __shared__ float Bs[16][65];
    const int tid = threadIdx.x;
    const int tx = tid & 15, ty = tid >> 4;
    const int m0 = mt * 64, n0 = nt * 64;
    float acc[4][4] = {};

    for (int k0 = 0; k0 < DIN; k0 += 16) {
        {
            int mm = tid >> 2, kk = (tid & 3) << 2;
            float4 v = *(const float4*)(x + (long)(m0 + mm) * DIN + k0 + kk);
            As[mm][kk] = v.x; As[mm][kk+1] = v.y; As[mm][kk+2] = v.z; As[mm][kk+3] = v.w;
        }
        {
            int kk = tid >> 4, nn = (tid & 15) << 2;
            float4 v = *(const float4*)(W + (long)(k0 + kk) * Dn + n0 + nn);
            Bs[kk][nn] = v.x; Bs[kk][nn+1] = v.y; Bs[kk][nn+2] = v.z; Bs[kk][nn+3] = v.w;
        }
        __syncthreads();
        #pragma unroll
        for (int kk = 0; kk < 16; kk++) {
            float a[4], b[4];
            #pragma unroll
            for (int r = 0; r < 4; r++) a[r] = As[ty*4 + r][kk];
            #pragma unroll
            for (int c = 0; c < 4; c++) b[c] = Bs[kk][tx + 16*c];
            #pragma unroll
            for (int r = 0; r < 4; r++)
                #pragma unroll
                for (int c = 0; c < 4; c++) acc[r][c] = fmaf(a[r], b[c], acc[r][c]);
        }
        __syncthreads();
    }
    #pragma unroll
    for (int r = 0; r < 4; r++) {
        int m = m0 + ty*4 + r;
        #pragma unroll
        for (int c = 0; c < 4; c++) {
            int n = n0 + tx + 16*c;
            float v = acc[r][c] + bias[n];
            v = (v > 0.f) ? v : 0.1f * v;
            C[(long)m * Dn + n] = v;
        }
    }
}

// ============================================================================
// FFMA2 GEMM engine v2: 64x64 tile, 256 threads, 4x4 micro (pair-packed cols),
// k-chunk 16.  A tile stored DUPLICATED in smem (As[k][2m]=As[k][2m+1]=a_m):
// inner k-step = 2x LDS.128 (A dup pairs) + 1x LDS.128 (B cols) + 8x FFMA2.
// Pitches: As 132 floats (528B, 16B-aligned rows), Bs 68 floats (272B).
// ============================================================================
__device__ __forceinline__ void gemm_tile_256(
    ull acc[4][2], float (*As)[132], float (*Bs)[68],
    const float* __restrict__ Ab, const float* __restrict__ Bb,
    int lda, int ldb, int m0, int n0, int bT, int K,
    int tid, int tx, int ty)
{
    const int mA = tid >> 2, kA = (tid & 3) << 2;
    const float* aLd = Ab + (long)(m0 + mA) * lda + kA;
    const float* bLd;
    if (!bT) bLd = Bb + (long)(tid >> 4) * ldb + n0 + (tid & 15) * 4;
    else     bLd = Bb + (long)(n0 + (tid >> 2)) * ldb + kA;

    float4 ra = *(const float4*)aLd;
    float4 rb = *(const float4*)bLd;

    const int nIter = K >> 4;
    for (int it = 0; it < nIter; it++) {
        // ---- stage regs -> smem ----
        {
            float av[4] = {ra.x, ra.y, ra.z, ra.w};
            #pragma unroll
            for (int i = 0; i < 4; i++)
                *(float2*)&As[kA + i][2*mA] = make_float2(av[i], av[i]);
        }
        if (!bT) {
            *(float4*)&Bs[tid >> 4][(tid & 15) * 4] = rb;
        } else {
            const int nB = tid >> 2;
            Bs[kA+0][nB] = rb.x; Bs[kA+1][nB] = rb.y;
            Bs[kA+2][nB] = rb.z; Bs[kA+3][nB] = rb.w;
        }
        __syncthreads();

        // ---- prefetch next tile ----
        if (it + 1 < nIter) {
            aLd += 16;
            ra = *(const float4*)aLd;
            if (!bT) bLd += (long)16 * ldb;
            else     bLd += 16;
            rb = *(const float4*)bLd;
        }

        // ---- compute 16 k-steps ----
        #pragma unroll
        for (int kk = 0; kk < 16; kk++) {
            F4U a01, a23, b;
            a01.f = *(const float4*)&As[kk][ty*8];
            a23.f = *(const float4*)&As[kk][ty*8 + 4];
            b.f   = *(const float4*)&Bs[kk][tx*4];
            ull av2[4] = {a01.u[0], a01.u[1], a23.u[0], a23.u[1]};
            ull bv[2]  = {b.u[0], b.u[1]};
            #pragma unroll
            for (int r = 0; r < 4; r++)
                #pragma unroll
                for (int c = 0; c < 2; c++)
                    acc[r][c] = ffma2(av2[r], bv[c], acc[r][c]);
        }
        __syncthreads();
    }
}

// Generic batched GEMM (direct C write).  grid(M/64, N/64, batch), 256 thr.
__global__ __launch_bounds__(256) void gemm256_kernel(
    const float* __restrict__ A, const float* __restrict__ Bm, float* __restrict__ C,
    int lda, int ldb, int ldc,
    int aDiv, long aStride, long bStride, long cStride, int bT, int K)
{
    const int mt = blockIdx.x, nt = blockIdx.y, z = blockIdx.z;
    const float* Ab = A + (long)(z / aDiv) * aStride;
    const float* Bb = Bm + (long)z * bStride;
    float* Cb = C + (long)z * cStride;
    const int m0 = mt * 64, n0 = nt * 64;
    const int tid = threadIdx.x, tx = tid & 15, ty = tid >> 4;

    __shared__ float As[16][132];
    __shared__ float Bs[16][68];
    ull acc[4][2] = {};

    gemm_tile_256(acc, As, Bs, Ab, Bb, lda, ldb, m0, n0, bT, K, tid, tx, ty);

    #pragma unroll
    for (int r = 0; r < 4; r++) {
        F4U o;
        o.u[0] = acc[r][0]; o.u[1] = acc[r][1];
        *(float4*)(Cb + (long)(m0 + ty*4 + r) * ldc + n0 + tx*4) = o.f;
    }
}

// Output GEMM (NT): s[q][m,n] = sum_k A[q][m,k] * Y[b][n,k].  M=N=Sn, K=128.
// sym=1: upper tiles only, write value + mirror.  grid(3,3,BSn), 256 thr.
__global__ __launch_bounds__(256) void gemm_out256_kernel(
    const float* __restrict__ A, const float* __restrict__ Y,
    float* __restrict__ Out, int sym)
{
    const int bx = blockIdx.x, by = blockIdx.y, q = blockIdx.z;
    if (sym && bx > by) return;
    const float* Ab = A + (long)q * (Sn * Dn);
    const float* Bb = Y + (long)(q / Sn) * (Sn * Dn);
    float* Ob = Out + (long)q * (Sn * Sn);
    const int m0 = bx * 64, n0 = by * 64;
    const int tid = threadIdx.x, tx = tid & 15, ty = tid >> 4;

    __shared__ float As[16][132];
    __shared__ float Bs[16][68];
    __shared__ float Cs[64][68];
    ull acc[4][2] = {};

    gemm_tile_256(acc, As, Bs, Ab, Bb, Dn, Dn, m0, n0, /*bT=*/1, Dn, tid, tx, ty);

    // stage C tile in smem (pitch 68 floats = 272B, 16B-aligned rows)
    #pragma unroll
    for (int r = 0; r < 4; r++) {
        F4U o;
        o.u[0] = acc[r][0]; o.u[1] = acc[r][1];
        *(float4*)&Cs[ty*4 + r][tx*4] = o.f;
    }
    __syncthreads();

    // write out: thread covers 4 consecutive cols (float4), 4 row-passes of 16
    const int c4 = (tid & 15) * 4;       // column group
    const int rg = tid >> 4;             // row offset within pass
    if (!sym) {
        #pragma unroll
        for (int i = 0; i < 4; i++) {
            int r = i*16 + rg;
            *(float4*)&Ob[(long)(m0 + r) * Sn + n0 + c4] = *(float4*)&Cs[r][c4];
        }
    } else if (bx < by) {
        #pragma unroll
        for (int i = 0; i < 4; i++) {
            int r = i*16 + rg;
            *(float4*)&Ob[(long)(m0 + r) * Sn + n0 + c4] = *(float4*)&Cs[r][c4];
            float4 t = make_float4(Cs[c4][r], Cs[c4+1][r], Cs[c4+2][r], Cs[c4+3][r]);
            *(float4*)&Ob[(long)(n0 + r) * Sn + m0 + c4] = t;
        }
    } else {  // diagonal tile
        #pragma unroll
        for (int i = 0; i < 4; i++) {
            int r = i*16 + rg;
            float4 v;
            v.x = (r <= c4  ) ? Cs[r][c4  ] : Cs[c4  ][r];
            v.y = (r <= c4+1) ? Cs[r][c4+1] : Cs[c4+1][r];
            v.z = (r <= c4+2) ? Cs[r][c4+2] : Cs[c4+2][r];
            v.w = (r <= c4+3) ? Cs[r][c4+3] : Cs[c4+3][r];
            *(float4*)&Ob[(long)(m0 + r) * Sn + n0 + c4] = v;
        }
    }
}

// ============================================================================
// pt_cop mirror pass over output layout [b,x,y,z]: for x>y, out[b,x,y,:] = out[b,y,x,:]
// ============================================================================
__global__ void mirror_kernel(float* __restrict__ Out)
{
    const int x = blockIdx.x, b = blockIdx.y;
    for (int y = 0; y < x; y++) {
        long dst = ((long)(b * Sn + x) * Sn + y) * Sn;
        long src = ((long)(b * Sn + y) * Sn + x) * Sn;
        for (int z = threadIdx.x; z < Sn; z += blockDim.x)
            Out[dst + z] = Out[src + z];
    }
}

// ============================================================================
extern "C" void kernel_launch(void* const* d_in, const int* in_sizes, int n_in,
                              void* d_out, int out_size)
{
    const float* x  = (const float*)d_in[0];
    const float* Wp = (const float*)d_in[1];
    const float* bp = (const float*)d_in[2];
    const float* Wh = (const float*)d_in[3];
    const float* bh = (const float*)d_in[4];
    const float* Wt = (const float*)d_in[5];
    const float* bt = (const float*)d_in[6];
    const float* W_span_ph = (const float*)d_in[7];
    const float* W_span_pt = (const float*)d_in[8];
    const float* W_ph_sib  = (const float*)d_in[9];
    const float* W_pt_sib  = (const float*)d_in[10];
    const float* W_ph_cop  = (const float*)d_in[11];
    const float* W_pt_cop  = (const float*)d_in[12];
    float* out = (float*)d_out;

    float *mlpP, *wzP, *tP;
    cudaGetSymbolAddress((void**)&mlpP, g_mlp);
    cudaGetSymbolAddress((void**)&wzP,  g_wz);
    cudaGetSymbolAddress((void**)&tP,   g_t);
    const float* p  = mlpP;
    const float* sh = mlpP + BSn * Dn;
    const float* st = mlpP + 2 * BSn * Dn;

    // p, sh, st
    mlp_kernel<<<dim3(6, 2, 3), 256>>>(x, Wp, bp, Wh, bh, Wt, bt);

    // ---- type 1 (sym, layout [b,z,x,y]): span_psh, span_pst, ph_sib, pt_sib ----
    const float* Ws1[4] = {W_span_ph, W_span_pt, W_ph_sib, W_pt_sib};
    const float* Xs1[4] = {sh, sh, sh, st};
    const float* Ys1[4] = {st, st, sh, st};
    for (int t = 0; t < 4; t++) {
        // wz[r, i, j] = sum_k p[r,k] * w[i,k,j]   (batch over i)
        gemm256_kernel<<<dim3(6, 2, 128), 256>>>(p, Ws1[t], wzP,
            Dn, Dn, Dn*Dn, 1, 0L, (long)Dn*Dn, (long)Dn, 0, Dn);
        // t[q, x, j] = sum_i X[b,x,i] * wz[q,i,j]  (NN, batch over q=(b,z))
        gemm256_kernel<<<dim3(3, 2, 384), 256>>>(Xs1[t], wzP, tP,
            Dn, Dn, Dn, Sn, (long)Sn*Dn, (long)Dn*Dn, (long)Sn*Dn, 0, Dn);
        // s[q, x, y] = sum_j t[q,x,j] * Y[b,y,j]   (NT, symmetrized write)
        gemm_out256_kernel<<<dim3(3, 3, 384), 256>>>(tP, Ys1[t], out + (long)t * SZo, 1);
    }

    // ---- type 2 (co-parent, layout [b,x,y,z]): ph_cop, pt_cop ----
    const float* Ws2[2] = {W_ph_cop, W_pt_cop};
    const float* Zs2[2] = {sh, st};
    for (int t = 0; t < 2; t++) {
        // u[r, k, j] = sum_i p[r,i] * w[i,k,j]    (batch over k)
        gemm256_kernel<<<dim3(6, 2, 128), 256>>>(p, Ws2[t], wzP,
            Dn, Dn*Dn, Dn*Dn, 1, 0L, (long)Dn, (long)Dn, 0, Dn);
        // v[q, y, k] = sum_j p[b,y,j] * u[q,k,j]  (NT, batch over q=(b,x))
        gemm256_kernel<<<dim3(3, 2, 384), 256>>>(p, wzP, tP,
            Dn, Dn, Dn, Sn, (long)Sn*Dn, (long)Dn*Dn, (long)Sn*Dn, 1, Dn);
        // out[q, y, z] = sum_k v[q,y,k] * Z[b,z,k] (NT, full write, z contiguous)
        gemm_out256_kernel<<<dim3(3, 3, 384), 256>>>(tP, Zs2[t], out + (long)(4 + t) * SZo, 0);
    }
    // pt_cop: sym over (x,y) crosses batch planes -> mirror pass
    mirror_kernel<<<dim3(Sn, Bn), 192>>>(out + 5 * SZo);
}